// round 15
// baseline (speedup 1.0000x reference)
#include <cuda_runtime.h>
#include <cuda_fp16.h>
#include <math.h>
#include <stdint.h>

// Problem constants
#define NB 16
#define LSEQ 128
#define DD 768
#define HH 8
#define JR 30
#define RR 49
#define NM 128       // N*M spans
#define NQ 3840      // NM*JR rows
#define SR 784       // NB*RR rows

// ---------------- scratch ----------------
__device__ __align__(16) half  g_enc_h [16 * 49 * 2048];
__device__ __align__(16) half  g_res_h [SR * DD];
__device__ __align__(16) half  g_kv_h  [SR * 2 * HH * DD];    // kproj|vproj [784,12288]
__device__ __align__(16) half  g_til_h [16 * SR * DD];        // ktil heads 0..7 | vtil heads 8..15
__device__ __align__(16) half  g_cat_h [NQ * 2 * DD];
__device__ __align__(16) half  g_h1_h  [NQ * 2 * DD];
__device__ __align__(16) half  g_f2_h  [NQ * DD];
__device__ __align__(16) half  g_pool_h[NM * DD];
__device__ __align__(16) uint32_t g_vtilP[16 * 224 * DD];     // [ns][kpair 224][d] packed pairs
// fp32 buffers
__device__ __align__(16) float g_ctx  [NQ * DD];
__device__ __align__(16) float g_t    [NM * DD];
// plain fp16 weights (B operands, [K][N] row-major)
__device__ __align__(16) half g_Walh [2048 * 768];
__device__ __align__(16) half g_Wkvh [768 * 12288];
__device__ __align__(16) half g_WTh  [16 * 768 * 768];        // WqT heads | Wfc blocks
__device__ __align__(16) half g_Wa1h [1536 * 1536];
__device__ __align__(16) half g_Wa2h [1536 * 768];
__device__ __align__(16) half g_Wdh  [768 * 768];

// ---------------- helpers ----------------
__device__ __forceinline__ uint32_t pack2(float a, float b) {
    __half2 h = __floats2half2_rn(a, b);
    return *(uint32_t*)&h;
}

__device__ __forceinline__ void mma16(float* c, const uint32_t* a, const uint32_t* b) {
    asm volatile(
        "mma.sync.aligned.m16n8k16.row.col.f32.f16.f16.f32 "
        "{%0,%1,%2,%3},{%4,%5,%6,%7},{%8,%9},{%0,%1,%2,%3};"
        : "+f"(c[0]), "+f"(c[1]), "+f"(c[2]), "+f"(c[3])
        : "r"(a[0]), "r"(a[1]), "r"(a[2]), "r"(a[3]), "r"(b[0]), "r"(b[1]));
}

__device__ __forceinline__ void ldsm4(uint32_t* r, uint32_t addr) {
    asm volatile("ldmatrix.sync.aligned.m8n8.x4.shared.b16 {%0,%1,%2,%3}, [%4];"
        : "=r"(r[0]), "=r"(r[1]), "=r"(r[2]), "=r"(r[3]) : "r"(addr));
}
__device__ __forceinline__ void ldsm4t(uint32_t* r, uint32_t addr) {
    asm volatile("ldmatrix.sync.aligned.m8n8.x4.trans.shared.b16 {%0,%1,%2,%3}, [%4];"
        : "=r"(r[0]), "=r"(r[1]), "=r"(r[2]), "=r"(r[3]) : "r"(addr));
}

__device__ __forceinline__ void cpa16(uint32_t saddr, const void* g) {
    asm volatile("cp.async.ca.shared.global [%0], [%1], 16;\n" :: "r"(saddr), "l"(g));
}
__device__ __forceinline__ void cpa_commit() {
    asm volatile("cp.async.commit_group;\n");
}
template<int N>
__device__ __forceinline__ void cpa_wait() {
    asm volatile("cp.async.wait_group %0;\n" :: "n"(N));
}

// ---------------- prep: generic fp32 -> fp16 convert (8 jobs) ----------------
struct CJob { const float* src; half* dst; int rows; int cols; int srcld; int dstld; };
struct CJobs { CJob j[8]; };

__global__ void convJobs(CJobs jobs) {
    CJob jb = jobs.j[blockIdx.y];
    int c4s = jb.cols >> 2;
    int total = jb.rows * c4s;
    for (int i = blockIdx.x * blockDim.x + threadIdx.x; i < total;
         i += gridDim.x * blockDim.x) {
        int r = i / c4s, c4 = i - r * c4s;
        float4 v = *(const float4*)(jb.src + (long long)r * jb.srcld + c4 * 4);
        __half2 h0 = __floats2half2_rn(v.x, v.y);
        __half2 h1 = __floats2half2_rn(v.z, v.w);
        uint2 u;
        u.x = *(uint32_t*)&h0;
        u.y = *(uint32_t*)&h1;
        *(uint2*)(jb.dst + (long long)r * jb.dstld + c4 * 4) = u;
    }
}

// Wq [768(j), 6144] -> WTh[h][d][j] = half(Wq[j][h*768+d])   (transposed head slice)
__global__ void transposeWqH(const float* __restrict__ Wq, half* __restrict__ WTh) {
    __shared__ float t[32][33];
    int h = blockIdx.z;
    int j0 = blockIdx.y * 32, d0 = blockIdx.x * 32;
    int tx = threadIdx.x, ty = threadIdx.y;   // 32 x 8
    #pragma unroll
    for (int dy = 0; dy < 32; dy += 8)
        t[ty + dy][tx] = Wq[(long long)(j0 + ty + dy) * 6144 + h * 768 + d0 + tx];
    __syncthreads();
    #pragma unroll
    for (int dy = 0; dy < 32; dy += 8)
        WTh[(long long)h * 768 * 768 + (long long)(d0 + ty + dy) * 768 + j0 + tx] =
            __float2half_rn(t[tx][ty + dy]);
}

// vtil (fp16, heads 8..15 of til) -> k-pair packed [ns][224][768] with zero pad r>=49
__global__ void vtilP_prep(const half* __restrict__ til, uint32_t* __restrict__ vp) {
    int total = 16 * 224 * DD;
    for (int i = blockIdx.x * blockDim.x + threadIdx.x; i < total;
         i += gridDim.x * blockDim.x) {
        int d = i % DD;
        int t = i / DD;
        int p = t % 224, ns = t / 224;
        int h = p / 28, rp = p - h * 28;
        int r0 = 2 * rp, r1 = 2 * rp + 1;
        const half* base = til + ((long long)(8 + h) * SR + ns * RR) * DD + d;
        half lo = (r0 < RR) ? base[(long long)r0 * DD] : __float2half(0.f);
        half hi = (r1 < RR) ? base[(long long)r1 * DD] : __float2half(0.f);
        __half2 u = __halves2half2(lo, hi);
        vp[i] = *(uint32_t*)&u;
    }
}

// ---------------- FP16 tensor-core GEMM, cp.async + ldmatrix -----------------
// BK=32 per stage (2 x k16 sub-blocks), NS=4 stages, ONE barrier/stage.
// A: half [M,K] row-major (M clamped). B: half [K,N] row-major. N%128==0, K%32==0.
#define STAGE_U32 5248
#define STAGE_BYTES (STAGE_U32 * 4)
#define GEMM_SMEM (4 * STAGE_BYTES)

template<int ACT, int OUTH>
__global__ __launch_bounds__(256, 2)
void gemmfp16(const half* __restrict__ A, const half* __restrict__ B,
              const float* __restrict__ bias, void* __restrict__ Cv,
              int M, int N, int K, int lda, int ldb, int ldc,
              long long aBS, long long bBS, long long cBS)
{
    constexpr int NS = 4;
    extern __shared__ uint32_t sm[];

    A += (long long)blockIdx.z * aBS;
    B += (long long)blockIdx.z * bBS;

    const int tid = threadIdx.x;
    const int warp = tid >> 5, lane = tid & 31;
    const int g = lane >> 2, tig = lane & 3;
    const int wm = warp & 1, wn = warp >> 1;     // 2x4 warps: 64x32 each
    const int bm = blockIdx.y * 128, bn = blockIdx.x * 128;

    // loaders
    const int la_row = tid >> 1, la_half = tid & 1;
    const half* aP = A + (long long)min(bm + la_row, M - 1) * lda + la_half * 8;
    const uint32_t a_off = la_row * 48 + la_half * 16;

    const int b_k0 = tid >> 4, b_seg = tid & 15;
    const half* bP = B + (long long)b_k0 * ldb + bn + b_seg * 8;
    const uint32_t b_off = 12288 + b_k0 * 272 + b_seg * 16;

    const uint32_t smbase = (uint32_t)__cvta_generic_to_shared(sm);

    // ldmatrix lane offsets
    const int rsel = (lane & 7) + ((lane >> 3) & 1) * 8;
    const uint32_t a_lane = rsel * 48 + (lane >> 4) * 16;
    const uint32_t b_lane = rsel * 272 + (lane >> 4) * 16;

    float acc[4][4][4];
    #pragma unroll
    for (int mt = 0; mt < 4; mt++)
        #pragma unroll
        for (int nt = 0; nt < 4; nt++)
            #pragma unroll
            for (int i = 0; i < 4; i++) acc[mt][nt][i] = 0.f;

    const int Kt = K >> 5;

    auto load_stage = [&](int buf, int kt) {
        uint32_t sb = smbase + buf * STAGE_BYTES;
        const half* ak = aP + kt * 32;
        const half* bk = bP + (long long)kt * 32 * ldb;
        cpa16(sb + a_off,        ak);
        cpa16(sb + 6144 + a_off, ak + 16);
        cpa16(sb + b_off,        bk);
        cpa16(sb + b_off + 4352, bk + (long long)16 * ldb);
    };

    load_stage(0, 0); cpa_commit();
    load_stage(1, 1); cpa_commit();
    load_stage(2, 2); cpa_commit();

    for (int kt = 0; kt < Kt; kt++) {
        cpa_wait<NS - 2>();
        __syncthreads();

        const int buf = kt & 3;
        const uint32_t sb = smbase + buf * STAGE_BYTES;

        #pragma unroll
        for (int s2 = 0; s2 < 2; s2++) {
            const uint32_t abase = sb + s2 * 6144 + wm * 64 * 48 + a_lane;
            const uint32_t bbase = sb + 12288 + s2 * 4352 + wn * 64 + b_lane;
            uint32_t af[4][4], bf[2][4];
            #pragma unroll
            for (int mt = 0; mt < 4; mt++)
                ldsm4(af[mt], abase + mt * 768);
            ldsm4t(bf[0], bbase);
            ldsm4t(bf[1], bbase + 32);
            #pragma unroll
            for (int mt = 0; mt < 4; mt++)
                #pragma unroll
                for (int nt = 0; nt < 4; nt++)
                    mma16(acc[mt][nt], af[mt], &bf[nt >> 1][(nt & 1) * 2]);
        }

        int nk = kt + NS - 1;
        if (nk < Kt) load_stage(nk & 3, nk);
        cpa_commit();
    }

    #pragma unroll
    for (int mt = 0; mt < 4; mt++) {
        int r0 = bm + wm * 64 + mt * 16 + g;
        int r1 = r0 + 8;
        #pragma unroll
        for (int nt = 0; nt < 4; nt++) {
            int c = bn + wn * 32 + nt * 8 + 2 * tig;
            float b0 = bias ? bias[c] : 0.f;
            float b1 = bias ? bias[c + 1] : 0.f;
            float v0 = acc[mt][nt][0] + b0, v1 = acc[mt][nt][1] + b1;
            float v2 = acc[mt][nt][2] + b0, v3 = acc[mt][nt][3] + b1;
            if (ACT == 1) { v0 = tanhf(v0); v1 = tanhf(v1); v2 = tanhf(v2); v3 = tanhf(v3); }
            if (OUTH) {
                half* C = (half*)Cv + (long long)blockIdx.z * cBS;
                if (r0 < M) *(uint32_t*)(C + (long long)r0 * ldc + c) = pack2(v0, v1);
                if (r1 < M) *(uint32_t*)(C + (long long)r1 * ldc + c) = pack2(v2, v3);
            } else {
                float* C = (float*)Cv + (long long)blockIdx.z * cBS;
                if (r0 < M) *(float2*)(C + (long long)r0 * ldc + c) = make_float2(v0, v1);
                if (r1 < M) *(float2*)(C + (long long)r1 * ldc + c) = make_float2(v2, v3);
            }
        }
    }
}

// ---------------- fused attention: QK^T + softmax + AV + residual ------------
// One CTA per span s. 8 warps; warp h owns head h in QK phase.
// Residual is read from cat's fp16 left half (span).
#define SP_OFF  0                    // span fp16: [32][388] u32 (rows 0..29 valid)
#define KT_OFF  12416                // QK: [8][56][36] u32 ; AV: [224][72] u32
#define P16_OFF 28544                // P fp16: [32][228] u32 (k = h*56+r)
#define LG_OFF  35840                // logits fp32: [8][32][58]
#define ATTN_SMEM ((35840 + 14848) * 4)   // 202752 B

__global__ __launch_bounds__(256, 1)
void fused_attn(const half* __restrict__ cat, const half* __restrict__ til,
                const uint32_t* __restrict__ vtilP, float* __restrict__ ctx)
{
    extern __shared__ uint32_t sm[];
    const int s = blockIdx.x;
    const int ns = s >> 3;
    const int tid = threadIdx.x, warp = tid >> 5, lane = tid & 31;
    const int g = lane >> 2, tig = lane & 3;
    const uint32_t smb = (uint32_t)__cvta_generic_to_shared(sm);

    // preload span tile (30 rows x 768 halves = 96 cpa16 per row)
    for (int i = tid; i < 30 * 96; i += 256) {
        int q = i / 96, j = i - q * 96;
        cpa16(smb + (SP_OFF + q * 388) * 4 + j * 16,
              cat + (long long)(s * JR + q) * 1536 + j * 8);
    }

    // ---- Phase A: logits ----
    float acc[2][7][4];
    #pragma unroll
    for (int mt = 0; mt < 2; mt++)
        #pragma unroll
        for (int nt = 0; nt < 7; nt++)
            #pragma unroll
            for (int i = 0; i < 4; i++) acc[mt][nt][i] = 0.f;

    const int h = warp;
    for (int kc = 0; kc < 12; kc++) {
        for (int i = tid; i < 8 * RR * 8; i += 256) {
            int hh = i / (RR * 8), rem = i - hh * (RR * 8);
            int r = rem >> 3, j = rem & 7;
            cpa16(smb + (KT_OFF + (hh * 56 + r) * 36) * 4 + j * 16,
                  til + ((long long)hh * SR + ns * RR + r) * DD + kc * 64 + j * 8);
        }
        cpa_commit();
        cpa_wait<0>();
        __syncthreads();

        const uint32_t* sp = sm + SP_OFF;
        const uint32_t* kt = sm + KT_OFF + h * 56 * 36;
        #pragma unroll
        for (int k4 = 0; k4 < 4; k4++) {
            uint32_t af[2][4], bf[7][2];
            #pragma unroll
            for (int mt = 0; mt < 2; mt++) {
                const uint32_t* p = sp + (mt * 16 + g) * 388 + kc * 32 + k4 * 8;
                af[mt][0] = p[tig];
                af[mt][1] = p[8 * 388 + tig];
                af[mt][2] = p[tig + 4];
                af[mt][3] = p[8 * 388 + tig + 4];
            }
            #pragma unroll
            for (int nt = 0; nt < 7; nt++) {
                bf[nt][0] = kt[(nt * 8 + g) * 36 + k4 * 8 + tig];
                bf[nt][1] = kt[(nt * 8 + g) * 36 + k4 * 8 + tig + 4];
            }
            #pragma unroll
            for (int mt = 0; mt < 2; mt++)
                #pragma unroll
                for (int nt = 0; nt < 7; nt++)
                    mma16(acc[mt][nt], af[mt], bf[nt]);
        }
        __syncthreads();
    }

    // store scaled logits to smem
    {
        float* lg = (float*)(sm + LG_OFF) + h * 32 * 58;
        const float scale = rsqrtf((float)DD);
        #pragma unroll
        for (int mt = 0; mt < 2; mt++) {
            int r0 = mt * 16 + g, r1 = r0 + 8;
            #pragma unroll
            for (int nt = 0; nt < 7; nt++) {
                int c = nt * 8 + 2 * tig;
                lg[r0 * 58 + c]     = acc[mt][nt][0] * scale;
                lg[r0 * 58 + c + 1] = acc[mt][nt][1] * scale;
                lg[r1 * 58 + c]     = acc[mt][nt][2] * scale;
                lg[r1 * 58 + c + 1] = acc[mt][nt][3] * scale;
            }
        }
    }
    __syncwarp();

    // ---- softmax (warp h handles its own head) ----
    {
        const float* lg = (const float*)(sm + LG_OFF) + h * 32 * 58;
        uint32_t* P = sm + P16_OFF;
        int rp = lane;
        for (int q = 0; q < JR; q++) {
            float v0 = -3.0e38f, v1 = -3.0e38f;
            if (rp < 25) {
                int r0 = 2 * rp, r1 = 2 * rp + 1;
                if (r0 < RR) v0 = lg[q * 58 + r0];
                if (r1 < RR) v1 = lg[q * 58 + r1];
            }
            float m = fmaxf(v0, v1);
            #pragma unroll
            for (int o = 16; o; o >>= 1) m = fmaxf(m, __shfl_xor_sync(0xffffffffu, m, o));
            float e0 = (v0 > -1.0e38f) ? expf(v0 - m) : 0.f;
            float e1 = (v1 > -1.0e38f) ? expf(v1 - m) : 0.f;
            float sum = e0 + e1;
            #pragma unroll
            for (int o = 16; o; o >>= 1) sum += __shfl_xor_sync(0xffffffffu, sum, o);
            float inv = 1.f / sum;
            if (rp < 28)
                P[q * 228 + h * 28 + rp] = pack2(e0 * inv, e1 * inv);
        }
    }
    __syncthreads();

    // ---- Phase B: ctx = P @ V + span(fp16 from cat) ----
    for (int dn = 0; dn < 12; dn++) {
        for (int i = tid; i < 224 * 16; i += 256) {
            int p = i >> 4, j = i & 15;
            cpa16(smb + (KT_OFF + p * 72) * 4 + j * 16,
                  vtilP + ((long long)ns * 224 + p) * DD + dn * 64 + j * 4);
        }
        cpa_commit();
        cpa_wait<0>();
        __syncthreads();

        float bacc[2][4];
        #pragma unroll
        for (int mt = 0; mt < 2; mt++)
            #pragma unroll
            for (int i = 0; i < 4; i++) bacc[mt][i] = 0.f;

        const uint32_t* Pp = sm + P16_OFF;
        const uint32_t* vp = sm + KT_OFF;
        #pragma unroll
        for (int k28 = 0; k28 < 28; k28++) {
            uint32_t af[2][4], bf[2];
            #pragma unroll
            for (int mt = 0; mt < 2; mt++) {
                const uint32_t* p = Pp + (mt * 16 + g) * 228 + k28 * 8;
                af[mt][0] = p[tig];
                af[mt][1] = p[8 * 228 + tig];
                af[mt][2] = p[tig + 4];
                af[mt][3] = p[8 * 228 + tig + 4];
            }
            bf[0] = vp[(k28 * 8 + tig) * 72 + warp * 8 + g];
            bf[1] = vp[(k28 * 8 + tig + 4) * 72 + warp * 8 + g];
            mma16(bacc[0], af[0], bf);
            mma16(bacc[1], af[1], bf);
        }

        #pragma unroll
        for (int mt = 0; mt < 2; mt++) {
            int r0 = mt * 16 + g, r1 = r0 + 8;
            int c = dn * 64 + warp * 8 + 2 * tig;
            if (r0 < JR) {
                uint32_t u = *(const uint32_t*)(cat + (long long)(s * JR + r0) * 1536 + c);
                float2 sp2 = __half22float2(*(__half2*)&u);
                *(float2*)(ctx + (long long)(s * JR + r0) * DD + c) =
                    make_float2(bacc[mt][0] + sp2.x, bacc[mt][1] + sp2.y);
            }
            if (r1 < JR) {
                uint32_t u = *(const uint32_t*)(cat + (long long)(s * JR + r1) * 1536 + c);
                float2 sp2 = __half22float2(*(__half2*)&u);
                *(float2*)(ctx + (long long)(s * JR + r1) * DD + c) =
                    make_float2(bacc[mt][2] + sp2.x, bacc[mt][3] + sp2.y);
            }
        }
        __syncthreads();
    }
}

// ---------------- span gather (fp16 -> cat left half only) ------------------
__global__ void gather_kernel(const float* __restrict__ seq,
                              const int* __restrict__ starts,
                              half* __restrict__ cat)
{
    int sq = blockIdx.x;
    int s = sq / JR, q = sq - s * JR;
    int gstart = starts[s] + (s >> 3) * LSEQ;
    int idx = min(gstart + q, NB * LSEQ - 1);
    const float4* src = (const float4*)(seq + (long long)idx * DD);
    uint2* dst2 = (uint2*)(cat + (long long)sq * 2 * DD);
    for (int i = threadIdx.x; i < DD / 4; i += blockDim.x) {
        float4 v = src[i];
        uint2 u;
        u.x = pack2(v.x, v.y);
        u.y = pack2(v.z, v.w);
        dst2[i] = u;
    }
}

// ---------------- layernorm (fp16 strided output into cat right) -----------
__global__ __launch_bounds__(256)
void ln_kernel(const float* __restrict__ X, const float* __restrict__ g,
               const float* __restrict__ b, half* __restrict__ Y, int ostride)
{
    int r = blockIdx.x;
    int t = threadIdx.x;
    const float* x = X + (long long)r * DD;
    float v0 = x[t], v1 = x[t + 256], v2 = x[t + 512];
    __shared__ float red[8];

    float s = v0 + v1 + v2;
    #pragma unroll
    for (int o = 16; o; o >>= 1) s += __shfl_xor_sync(0xffffffffu, s, o);
    if ((t & 31) == 0) red[t >> 5] = s;
    __syncthreads();
    if (t == 0) { float z = 0.f; for (int i = 0; i < 8; i++) z += red[i]; red[0] = z; }
    __syncthreads();
    float mu = red[0] * (1.0f / DD);
    __syncthreads();

    float d0 = v0 - mu, d1 = v1 - mu, d2 = v2 - mu;
    float ss = d0 * d0 + d1 * d1 + d2 * d2;
    #pragma unroll
    for (int o = 16; o; o >>= 1) ss += __shfl_xor_sync(0xffffffffu, ss, o);
    if ((t & 31) == 0) red[t >> 5] = ss;
    __syncthreads();
    if (t == 0) { float z = 0.f; for (int i = 0; i < 8; i++) z += red[i]; red[0] = z; }
    __syncthreads();
    float inv = rsqrtf(red[0] * (1.0f / DD) + 1e-5f);

    half* y = Y + (long long)r * ostride;
    y[t]       = __float2half_rn(d0 * inv * g[t]       + b[t]);
    y[t + 256] = __float2half_rn(d1 * inv * g[t + 256] + b[t + 256]);
    y[t + 512] = __float2half_rn(d2 * inv * g[t + 512] + b[t + 512]);
}

// ---------------- unary score + masked softmax + pooling (fp16 input) -------
__global__ __launch_bounds__(256)
void pool_kernel(const half* __restrict__ F2, const float* __restrict__ W_un,
                 const float* __restrict__ b_un, const int* __restrict__ starts,
                 const int* __restrict__ ends, half* __restrict__ pooled)
{
    int s = blockIdx.x;
    __shared__ float sc[JR];
    __shared__ float pr[32];
    int tid = threadIdx.x, warp = tid >> 5, lane = tid & 31;

    for (int q = warp; q < JR; q += 8) {
        const half* row = F2 + (long long)(s * JR + q) * DD;
        float acc = 0.f;
        for (int k = lane; k < DD; k += 32) acc += __half2float(row[k]) * W_un[k];
        #pragma unroll
        for (int o = 16; o; o >>= 1) acc += __shfl_xor_sync(0xffffffffu, acc, o);
        if (lane == 0) sc[q] = acc + b_un[0];
    }
    __syncthreads();

    if (tid < 32) {
        int width = ends[s] - starts[s] + 1;
        float v = -3.0e38f;
        if (tid < JR) {
            v = sc[tid];
            if (tid >= width) v += -10000.0f;
        }
        float m = v;
        #pragma unroll
        for (int o = 16; o; o >>= 1) m = fmaxf(m, __shfl_xor_sync(0xffffffffu, m, o));
        float e = (tid < JR) ? expf(v - m) : 0.f;
        float sum = e;
        #pragma unroll
        for (int o = 16; o; o >>= 1) sum += __shfl_xor_sync(0xffffffffu, sum, o);
        pr[tid] = (tid < JR) ? e / sum : 0.f;
    }
    __syncthreads();

    for (int o = tid; o < DD; o += 256) {
        float acc = 0.f;
        #pragma unroll
        for (int q = 0; q < JR; q++)
            acc += pr[q] * __half2float(F2[(long long)(s * JR + q) * DD + o]);
        pooled[(long long)s * DD + o] = __float2half_rn(acc);
    }
}

// ---------------- classifier ------------------------------------------------
__global__ void cls_kernel(const float* __restrict__ T, const float* __restrict__ Wc,
                           const float* __restrict__ bc, float* __restrict__ out)
{
    int s = blockIdx.x;
    int c = threadIdx.x >> 5, lane = threadIdx.x & 31;
    const float* t = T + (long long)s * DD;
    float acc = 0.f;
    for (int k = lane; k < DD; k += 32) acc += t[k] * Wc[k * 4 + c];
    #pragma unroll
    for (int o = 16; o; o >>= 1) acc += __shfl_xor_sync(0xffffffffu, acc, o);
    if (lane == 0) out[s * 4 + c] = acc + bc[c];
}

// ---------------- launcher --------------------------------------------------
extern "C" void kernel_launch(void* const* d_in, const int* in_sizes, int n_in,
                              void* d_out, int out_size)
{
    const float* enc_img  = (const float*)d_in[0];
    const float* seq      = (const float*)d_in[1];
    const int*   starts   = (const int*)d_in[3];
    const int*   ends     = (const int*)d_in[4];
    const float* W_align  = (const float*)d_in[5];
    const float* b_align  = (const float*)d_in[6];
    const float* Wq       = (const float*)d_in[7];
    const float* Wk       = (const float*)d_in[8];
    const float* Wv       = (const float*)d_in[9];
    const float* Wfc      = (const float*)d_in[10];
    const float* ln_g     = (const float*)d_in[11];
    const float* ln_b     = (const float*)d_in[12];
    const float* W_a1     = (const float*)d_in[13];
    const float* b_a1     = (const float*)d_in[14];
    const float* W_a2     = (const float*)d_in[15];
    const float* b_a2     = (const float*)d_in[16];
    const float* W_un     = (const float*)d_in[17];
    const float* b_un     = (const float*)d_in[18];
    const float* W_dense  = (const float*)d_in[19];
    const float* b_dense  = (const float*)d_in[20];
    const float* W_cls    = (const float*)d_in[21];
    const float* b_cls    = (const float*)d_in[22];
    float* out = (float*)d_out;

    half *ench, *resh, *kvh, *tilh, *cath, *h1h, *f2h, *poolh;
    half *walh, *wkvh, *wth, *wa1h, *wa2h, *wdh;
    float *ctx, *tb;
    uint32_t *vtp;
    cudaGetSymbolAddress((void**)&ench,  g_enc_h);
    cudaGetSymbolAddress((void**)&resh,  g_res_h);
    cudaGetSymbolAddress((void**)&kvh,   g_kv_h);
    cudaGetSymbolAddress((void**)&tilh,  g_til_h);
    cudaGetSymbolAddress((void**)&cath,  g_cat_h);
    cudaGetSymbolAddress((void**)&h1h,   g_h1_h);
    cudaGetSymbolAddress((void**)&f2h,   g_f2_h);
    cudaGetSymbolAddress((void**)&poolh, g_pool_h);
    cudaGetSymbolAddress((void**)&ctx,   g_ctx);
    cudaGetSymbolAddress((void**)&tb,    g_t);
    cudaGetSymbolAddress((void**)&walh,  g_Walh);
    cudaGetSymbolAddress((void**)&wkvh,  g_Wkvh);
    cudaGetSymbolAddress((void**)&wth,   g_WTh);
    cudaGetSymbolAddress((void**)&wa1h,  g_Wa1h);
    cudaGetSymbolAddress((void**)&wa2h,  g_Wa2h);
    cudaGetSymbolAddress((void**)&wdh,   g_Wdh);
    cudaGetSymbolAddress((void**)&vtp,   g_vtilP);

    cudaFuncSetAttribute(gemmfp16<0, 0>, cudaFuncAttributeMaxDynamicSharedMemorySize, GEMM_SMEM);
    cudaFuncSetAttribute(gemmfp16<0, 1>, cudaFuncAttributeMaxDynamicSharedMemorySize, GEMM_SMEM);
    cudaFuncSetAttribute(gemmfp16<1, 0>, cudaFuncAttributeMaxDynamicSharedMemorySize, GEMM_SMEM);
    cudaFuncSetAttribute(gemmfp16<1, 1>, cudaFuncAttributeMaxDynamicSharedMemorySize, GEMM_SMEM);
    cudaFuncSetAttribute(fused_attn, cudaFuncAttributeMaxDynamicSharedMemorySize, ATTN_SMEM);

    // prep: fp32 -> fp16 conversions (8 plain jobs) + Wq head transpose
    CJobs cj;
    cj.j[0] = { enc_img, ench, 16 * 49, 2048, 2048, 2048 };
    cj.j[1] = { W_align, walh, 2048, 768, 768, 768 };
    cj.j[2] = { Wk, wkvh, 768, 6144, 6144, 12288 };
    cj.j[3] = { Wv, wkvh + 6144, 768, 6144, 6144, 12288 };
    cj.j[4] = { Wfc, wth + 8LL * 768 * 768, 6144, 768, 768, 768 };
    cj.j[5] = { W_a1, wa1h, 1536, 1536, 1536, 1536 };
    cj.j[6] = { W_a2, wa2h, 1536, 768, 768, 768 };
    cj.j[7] = { W_dense, wdh, 768, 768, 768, 768 };
    convJobs<<<dim3(256, 8), 256>>>(cj);
    transposeWqH<<<dim3(24, 24, 8), dim3(32, 8)>>>(Wq, wth);

    // 0) res = enc_img @ W_align + b_align  (single GEMM, K=2048, half out)
    gemmfp16<0, 1><<<dim3(6, 7, 1), 256, GEMM_SMEM>>>(
        ench, walh, b_align, resh, SR, 768, 2048, 2048, 768, 768, 0, 0, 0);

    // 1) kvproj = res @ [Wk|Wv]     [784,12288] half out
    gemmfp16<0, 1><<<dim3(96, 7, 1), 256, GEMM_SMEM>>>(
        resh, wkvh, nullptr, kvh, SR, 12288, 768, 768, 12288, 12288, 0, 0, 0);
    // 2) til (fp16): z<8 ktil_h = kproj_h @ WqT_h; z>=8 vtil_h = vproj_h @ Wfc_h
    gemmfp16<0, 1><<<dim3(6, 7, 16), 256, GEMM_SMEM>>>(
        kvh, wth, nullptr, tilh, SR, 768, 768, 12288, 768, 768,
        768LL, 768LL * 768LL, (long long)SR * 768);
    // 3) span gather (fp16 cat-left only)
    gather_kernel<<<NQ, 192>>>(seq, starts, cath);
    // 4) vtil pack for AV
    vtilP_prep<<<2048, 256>>>(tilh, vtp);
    // 5) fused attention -> ctx (residual from cat fp16)
    fused_attn<<<NM, 256, ATTN_SMEM>>>(cath, tilh, vtp, ctx);
    // 6) layernorm -> cat right half
    ln_kernel<<<NQ, 256>>>(ctx, ln_g, ln_b, cath + DD, 2 * DD);
    // 7) h1 = tanh(cat @ W_a1 + b_a1)
    gemmfp16<1, 1><<<dim3(12, 30, 1), 256, GEMM_SMEM>>>(
        cath, wa1h, b_a1, h1h, NQ, 1536, 1536, 1536, 1536, 1536, 0, 0, 0);
    // 8) f2 = h1 @ W_a2 + b_a2  (half out)
    gemmfp16<0, 1><<<dim3(6, 30, 1), 256, GEMM_SMEM>>>(
        h1h, wa2h, b_a2, f2h, NQ, 768, 1536, 1536, 768, 768, 0, 0, 0);
    // 9) pool (fp16 input)
    pool_kernel<<<NM, 256>>>(f2h, W_un, b_un, starts, ends, poolh);
    // 10) dense
    gemmfp16<1, 0><<<dim3(6, 1, 1), 256, GEMM_SMEM>>>(
        poolh, wdh, b_dense, tb, NM, 768, 768, 768, 768, 768, 0, 0, 0);
    // 11) classifier
    cls_kernel<<<NM, 128>>>(tb, W_cls, b_cls, out);
}

// round 16
// speedup vs baseline: 1.4104x; 1.4104x over previous
#include <cuda_runtime.h>
#include <cuda_fp16.h>
#include <math.h>
#include <stdint.h>

// Problem constants
#define NB 16
#define LSEQ 128
#define DD 768
#define HH 8
#define JR 30
#define RR 49
#define NM 128       // N*M spans
#define NQ 3840      // NM*JR rows
#define SR 784       // NB*RR rows

// ---------------- scratch ----------------
__device__ __align__(16) half  g_enc_h [16 * 49 * 2048];
__device__ __align__(16) half  g_res_h [SR * DD];
__device__ __align__(16) half  g_kv_h  [SR * 2 * HH * DD];    // kproj|vproj [784,12288]
__device__ __align__(16) half  g_til_h [16 * SR * DD];        // ktil heads 0..7 | vtil heads 8..15
__device__ __align__(16) half  g_cat_h [NQ * 2 * DD];
__device__ __align__(16) half  g_h1_h  [NQ * 2 * DD];
__device__ __align__(16) half  g_pool_h[NM * DD];
__device__ __align__(16) uint32_t g_vtilP[16 * 224 * DD];     // [ns][kpair 224][d] packed pairs
// fp32 buffers
__device__ __align__(16) float g_span [NQ * DD];
__device__ __align__(16) float g_ctx  [NQ * DD];              // also res split-K partials
__device__ __align__(16) float g_f2   [NQ * DD];
__device__ __align__(16) float g_t    [NM * DD];
// plain fp16 weights (B operands, [K][N] row-major)
__device__ __align__(16) half g_Walh [2048 * 768];
__device__ __align__(16) half g_Wkvh [768 * 12288];
__device__ __align__(16) half g_WTh  [16 * 768 * 768];        // WqT heads | Wfc blocks
__device__ __align__(16) half g_Wa1h [1536 * 1536];
__device__ __align__(16) half g_Wa2h [1536 * 768];
__device__ __align__(16) half g_Wdh  [768 * 768];

// ---------------- helpers ----------------
__device__ __forceinline__ uint32_t pack2(float a, float b) {
    __half2 h = __floats2half2_rn(a, b);
    return *(uint32_t*)&h;
}

__device__ __forceinline__ void mma16(float* c, const uint32_t* a, const uint32_t* b) {
    asm volatile(
        "mma.sync.aligned.m16n8k16.row.col.f32.f16.f16.f32 "
        "{%0,%1,%2,%3},{%4,%5,%6,%7},{%8,%9},{%0,%1,%2,%3};"
        : "+f"(c[0]), "+f"(c[1]), "+f"(c[2]), "+f"(c[3])
        : "r"(a[0]), "r"(a[1]), "r"(a[2]), "r"(a[3]), "r"(b[0]), "r"(b[1]));
}

__device__ __forceinline__ void ldsm4(uint32_t* r, uint32_t addr) {
    asm volatile("ldmatrix.sync.aligned.m8n8.x4.shared.b16 {%0,%1,%2,%3}, [%4];"
        : "=r"(r[0]), "=r"(r[1]), "=r"(r[2]), "=r"(r[3]) : "r"(addr));
}
__device__ __forceinline__ void ldsm4t(uint32_t* r, uint32_t addr) {
    asm volatile("ldmatrix.sync.aligned.m8n8.x4.trans.shared.b16 {%0,%1,%2,%3}, [%4];"
        : "=r"(r[0]), "=r"(r[1]), "=r"(r[2]), "=r"(r[3]) : "r"(addr));
}

__device__ __forceinline__ void cpa16(uint32_t saddr, const void* g) {
    asm volatile("cp.async.ca.shared.global [%0], [%1], 16;\n" :: "r"(saddr), "l"(g));
}
__device__ __forceinline__ void cpa_commit() {
    asm volatile("cp.async.commit_group;\n");
}
template<int N>
__device__ __forceinline__ void cpa_wait() {
    asm volatile("cp.async.wait_group %0;\n" :: "n"(N));
}

// ---------------- prep: generic fp32 -> fp16 convert (8 jobs) ----------------
struct CJob { const float* src; half* dst; int rows; int cols; int srcld; int dstld; };
struct CJobs { CJob j[8]; };

__global__ void convJobs(CJobs jobs) {
    CJob jb = jobs.j[blockIdx.y];
    int c4s = jb.cols >> 2;
    int total = jb.rows * c4s;
    for (int i = blockIdx.x * blockDim.x + threadIdx.x; i < total;
         i += gridDim.x * blockDim.x) {
        int r = i / c4s, c4 = i - r * c4s;
        float4 v = *(const float4*)(jb.src + (long long)r * jb.srcld + c4 * 4);
        __half2 h0 = __floats2half2_rn(v.x, v.y);
        __half2 h1 = __floats2half2_rn(v.z, v.w);
        uint2 u;
        u.x = *(uint32_t*)&h0;
        u.y = *(uint32_t*)&h1;
        *(uint2*)(jb.dst + (long long)r * jb.dstld + c4 * 4) = u;
    }
}

// Wq [768(j), 6144] -> WTh[h][d][j] = half(Wq[j][h*768+d])   (transposed head slice)
__global__ void transposeWqH(const float* __restrict__ Wq, half* __restrict__ WTh) {
    __shared__ float t[32][33];
    int h = blockIdx.z;
    int j0 = blockIdx.y * 32, d0 = blockIdx.x * 32;
    int tx = threadIdx.x, ty = threadIdx.y;   // 32 x 8
    #pragma unroll
    for (int dy = 0; dy < 32; dy += 8)
        t[ty + dy][tx] = Wq[(long long)(j0 + ty + dy) * 6144 + h * 768 + d0 + tx];
    __syncthreads();
    #pragma unroll
    for (int dy = 0; dy < 32; dy += 8)
        WTh[(long long)h * 768 * 768 + (long long)(d0 + ty + dy) * 768 + j0 + tx] =
            __float2half_rn(t[tx][ty + dy]);
}

// vtil (fp16, heads 8..15 of til) -> k-pair packed [ns][224][768] with zero pad r>=49
__global__ void vtilP_prep(const half* __restrict__ til, uint32_t* __restrict__ vp) {
    int total = 16 * 224 * DD;
    for (int i = blockIdx.x * blockDim.x + threadIdx.x; i < total;
         i += gridDim.x * blockDim.x) {
        int d = i % DD;
        int t = i / DD;
        int p = t % 224, ns = t / 224;
        int h = p / 28, rp = p - h * 28;
        int r0 = 2 * rp, r1 = 2 * rp + 1;
        const half* base = til + ((long long)(8 + h) * SR + ns * RR) * DD + d;
        half lo = (r0 < RR) ? base[(long long)r0 * DD] : __float2half(0.f);
        half hi = (r1 < RR) ? base[(long long)r1 * DD] : __float2half(0.f);
        __half2 u = __halves2half2(lo, hi);
        vp[i] = *(uint32_t*)&u;
    }
}

// res split-K combine: resh = half(p0 + p1 + bias)
__global__ void resc_kernel(const float* __restrict__ p0, const float* __restrict__ p1,
                            const float* __restrict__ bias, half* __restrict__ out) {
    int i = blockIdx.x * blockDim.x + threadIdx.x;
    if (i < SR * DD) out[i] = __float2half_rn(p0[i] + p1[i] + bias[i % DD]);
}

// ---------------- FP16 tensor-core GEMM, cp.async + ldmatrix -----------------
// BK=32 per stage (2 x k16 sub-blocks), NS=5 stages, ONE barrier/stage.
// Next-stage loads issue BEFORE compute (right after the barrier that frees
// the target buffer), maximizing load/compute overlap.
// A: half [M,K] row-major (M clamped). B: half [K,N] row-major. N%128==0, K%32==0.
#define STAGE_U32 5248
#define STAGE_BYTES (STAGE_U32 * 4)
#define GEMM_SMEM (5 * STAGE_BYTES)

template<int ACT, int OUTH>
__global__ __launch_bounds__(256, 2)
void gemmfp16(const half* __restrict__ A, const half* __restrict__ B,
              const float* __restrict__ bias, void* __restrict__ Cv,
              int M, int N, int K, int lda, int ldb, int ldc,
              long long aBS, long long bBS, long long cBS)
{
    constexpr int NS = 5;
    extern __shared__ uint32_t sm[];

    A += (long long)blockIdx.z * aBS;
    B += (long long)blockIdx.z * bBS;

    const int tid = threadIdx.x;
    const int warp = tid >> 5, lane = tid & 31;
    const int g = lane >> 2, tig = lane & 3;
    const int wm = warp & 1, wn = warp >> 1;     // 2x4 warps: 64x32 each
    const int bm = blockIdx.y * 128, bn = blockIdx.x * 128;

    // loaders
    const int la_row = tid >> 1, la_half = tid & 1;
    const half* aP = A + (long long)min(bm + la_row, M - 1) * lda + la_half * 8;
    const uint32_t a_off = la_row * 48 + la_half * 16;

    const int b_k0 = tid >> 4, b_seg = tid & 15;
    const half* bP = B + (long long)b_k0 * ldb + bn + b_seg * 8;
    const uint32_t b_off = 12288 + b_k0 * 272 + b_seg * 16;

    const uint32_t smbase = (uint32_t)__cvta_generic_to_shared(sm);

    // ldmatrix lane offsets
    const int rsel = (lane & 7) + ((lane >> 3) & 1) * 8;
    const uint32_t a_lane = rsel * 48 + (lane >> 4) * 16;
    const uint32_t b_lane = rsel * 272 + (lane >> 4) * 16;

    float acc[4][4][4];
    #pragma unroll
    for (int mt = 0; mt < 4; mt++)
        #pragma unroll
        for (int nt = 0; nt < 4; nt++)
            #pragma unroll
            for (int i = 0; i < 4; i++) acc[mt][nt][i] = 0.f;

    const int Kt = K >> 5;

    auto load_stage = [&](int buf, int kt) {
        uint32_t sb = smbase + buf * STAGE_BYTES;
        const half* ak = aP + kt * 32;
        const half* bk = bP + (long long)kt * 32 * ldb;
        cpa16(sb + a_off,        ak);
        cpa16(sb + 6144 + a_off, ak + 16);
        cpa16(sb + b_off,        bk);
        cpa16(sb + b_off + 4352, bk + (long long)16 * ldb);
    };

    // prologue: NS-1 = 4 stages in flight
    load_stage(0, 0); cpa_commit();
    load_stage(1, 1); cpa_commit();
    load_stage(2, 2); cpa_commit();
    load_stage(3, 3); cpa_commit();

    for (int kt = 0; kt < Kt; kt++) {
        cpa_wait<NS - 2>();
        __syncthreads();     // stage kt visible; buffer (kt-1)%NS now free

        // issue next-stage loads FIRST so they overlap with compute below
        int nk = kt + NS - 1;
        if (nk < Kt) load_stage(nk % NS, nk);
        cpa_commit();

        const int buf = kt % NS;
        const uint32_t sb = smbase + buf * STAGE_BYTES;

        #pragma unroll
        for (int s2 = 0; s2 < 2; s2++) {
            const uint32_t abase = sb + s2 * 6144 + wm * 64 * 48 + a_lane;
            const uint32_t bbase = sb + 12288 + s2 * 4352 + wn * 64 + b_lane;
            uint32_t af[4][4], bf[2][4];
            #pragma unroll
            for (int mt = 0; mt < 4; mt++)
                ldsm4(af[mt], abase + mt * 768);
            ldsm4t(bf[0], bbase);
            ldsm4t(bf[1], bbase + 32);
            #pragma unroll
            for (int mt = 0; mt < 4; mt++)
                #pragma unroll
                for (int nt = 0; nt < 4; nt++)
                    mma16(acc[mt][nt], af[mt], &bf[nt >> 1][(nt & 1) * 2]);
        }
    }

    #pragma unroll
    for (int mt = 0; mt < 4; mt++) {
        int r0 = bm + wm * 64 + mt * 16 + g;
        int r1 = r0 + 8;
        #pragma unroll
        for (int nt = 0; nt < 4; nt++) {
            int c = bn + wn * 32 + nt * 8 + 2 * tig;
            float b0 = bias ? bias[c] : 0.f;
            float b1 = bias ? bias[c + 1] : 0.f;
            float v0 = acc[mt][nt][0] + b0, v1 = acc[mt][nt][1] + b1;
            float v2 = acc[mt][nt][2] + b0, v3 = acc[mt][nt][3] + b1;
            if (ACT == 1) { v0 = tanhf(v0); v1 = tanhf(v1); v2 = tanhf(v2); v3 = tanhf(v3); }
            if (OUTH) {
                half* C = (half*)Cv + (long long)blockIdx.z * cBS;
                if (r0 < M) *(uint32_t*)(C + (long long)r0 * ldc + c) = pack2(v0, v1);
                if (r1 < M) *(uint32_t*)(C + (long long)r1 * ldc + c) = pack2(v2, v3);
            } else {
                float* C = (float*)Cv + (long long)blockIdx.z * cBS;
                if (r0 < M) *(float2*)(C + (long long)r0 * ldc + c) = make_float2(v0, v1);
                if (r1 < M) *(float2*)(C + (long long)r1 * ldc + c) = make_float2(v2, v3);
            }
        }
    }
}

// ---------------- fused attention: QK^T + softmax + AV + residual ------------
// One CTA per span s. 8 warps; warp h owns head h in QK phase.
#define SP_OFF  0                    // span fp16: [32][388] u32 (rows 0..29 valid)
#define KT_OFF  12416                // QK: [8][56][36] u32 ; AV: [224][72] u32
#define P16_OFF 28544                // P fp16: [32][228] u32 (k = h*56+r)
#define LG_OFF  35840                // logits fp32: [8][32][58]
#define ATTN_SMEM ((35840 + 14848) * 4)   // 202752 B

__global__ __launch_bounds__(256, 1)
void fused_attn(const half* __restrict__ cat, const half* __restrict__ til,
                const uint32_t* __restrict__ vtilP, const float* __restrict__ span,
                float* __restrict__ ctx)
{
    extern __shared__ uint32_t sm[];
    const int s = blockIdx.x;
    const int ns = s >> 3;
    const int tid = threadIdx.x, warp = tid >> 5, lane = tid & 31;
    const int g = lane >> 2, tig = lane & 3;
    const uint32_t smb = (uint32_t)__cvta_generic_to_shared(sm);

    // preload span tile (30 rows x 768 halves = 96 cpa16 per row)
    for (int i = tid; i < 30 * 96; i += 256) {
        int q = i / 96, j = i - q * 96;
        cpa16(smb + (SP_OFF + q * 388) * 4 + j * 16,
              cat + (long long)(s * JR + q) * 1536 + j * 8);
    }

    // ---- Phase A: logits ----
    float acc[2][7][4];
    #pragma unroll
    for (int mt = 0; mt < 2; mt++)
        #pragma unroll
        for (int nt = 0; nt < 7; nt++)
            #pragma unroll
            for (int i = 0; i < 4; i++) acc[mt][nt][i] = 0.f;

    const int h = warp;
    for (int kc = 0; kc < 12; kc++) {
        for (int i = tid; i < 8 * RR * 8; i += 256) {
            int hh = i / (RR * 8), rem = i - hh * (RR * 8);
            int r = rem >> 3, j = rem & 7;
            cpa16(smb + (KT_OFF + (hh * 56 + r) * 36) * 4 + j * 16,
                  til + ((long long)hh * SR + ns * RR + r) * DD + kc * 64 + j * 8);
        }
        cpa_commit();
        cpa_wait<0>();
        __syncthreads();

        const uint32_t* sp = sm + SP_OFF;
        const uint32_t* kt = sm + KT_OFF + h * 56 * 36;
        #pragma unroll
        for (int k4 = 0; k4 < 4; k4++) {
            uint32_t af[2][4], bf[7][2];
            #pragma unroll
            for (int mt = 0; mt < 2; mt++) {
                const uint32_t* p = sp + (mt * 16 + g) * 388 + kc * 32 + k4 * 8;
                af[mt][0] = p[tig];
                af[mt][1] = p[8 * 388 + tig];
                af[mt][2] = p[tig + 4];
                af[mt][3] = p[8 * 388 + tig + 4];
            }
            #pragma unroll
            for (int nt = 0; nt < 7; nt++) {
                bf[nt][0] = kt[(nt * 8 + g) * 36 + k4 * 8 + tig];
                bf[nt][1] = kt[(nt * 8 + g) * 36 + k4 * 8 + tig + 4];
            }
            #pragma unroll
            for (int mt = 0; mt < 2; mt++)
                #pragma unroll
                for (int nt = 0; nt < 7; nt++)
                    mma16(acc[mt][nt], af[mt], bf[nt]);
        }
        __syncthreads();
    }

    // store scaled logits to smem
    {
        float* lg = (float*)(sm + LG_OFF) + h * 32 * 58;
        const float scale = rsqrtf((float)DD);
        #pragma unroll
        for (int mt = 0; mt < 2; mt++) {
            int r0 = mt * 16 + g, r1 = r0 + 8;
            #pragma unroll
            for (int nt = 0; nt < 7; nt++) {
                int c = nt * 8 + 2 * tig;
                lg[r0 * 58 + c]     = acc[mt][nt][0] * scale;
                lg[r0 * 58 + c + 1] = acc[mt][nt][1] * scale;
                lg[r1 * 58 + c]     = acc[mt][nt][2] * scale;
                lg[r1 * 58 + c + 1] = acc[mt][nt][3] * scale;
            }
        }
    }
    __syncwarp();

    // ---- softmax (warp h handles its own head) ----
    {
        const float* lg = (const float*)(sm + LG_OFF) + h * 32 * 58;
        uint32_t* P = sm + P16_OFF;
        int rp = lane;
        for (int q = 0; q < JR; q++) {
            float v0 = -3.0e38f, v1 = -3.0e38f;
            if (rp < 25) {
                int r0 = 2 * rp, r1 = 2 * rp + 1;
                if (r0 < RR) v0 = lg[q * 58 + r0];
                if (r1 < RR) v1 = lg[q * 58 + r1];
            }
            float m = fmaxf(v0, v1);
            #pragma unroll
            for (int o = 16; o; o >>= 1) m = fmaxf(m, __shfl_xor_sync(0xffffffffu, m, o));
            float e0 = (v0 > -1.0e38f) ? expf(v0 - m) : 0.f;
            float e1 = (v1 > -1.0e38f) ? expf(v1 - m) : 0.f;
            float sum = e0 + e1;
            #pragma unroll
            for (int o = 16; o; o >>= 1) sum += __shfl_xor_sync(0xffffffffu, sum, o);
            float inv = 1.f / sum;
            if (rp < 28)
                P[q * 228 + h * 28 + rp] = pack2(e0 * inv, e1 * inv);
        }
    }
    __syncthreads();

    // ---- Phase B: ctx = P @ V + span ----
    for (int dn = 0; dn < 12; dn++) {
        for (int i = tid; i < 224 * 16; i += 256) {
            int p = i >> 4, j = i & 15;
            cpa16(smb + (KT_OFF + p * 72) * 4 + j * 16,
                  vtilP + ((long long)ns * 224 + p) * DD + dn * 64 + j * 4);
        }
        cpa_commit();
        cpa_wait<0>();
        __syncthreads();

        float bacc[2][4];
        #pragma unroll
        for (int mt = 0; mt < 2; mt++)
            #pragma unroll
            for (int i = 0; i < 4; i++) bacc[mt][i] = 0.f;

        const uint32_t* Pp = sm + P16_OFF;
        const uint32_t* vp = sm + KT_OFF;
        #pragma unroll
        for (int k28 = 0; k28 < 28; k28++) {
            uint32_t af[2][4], bf[2];
            #pragma unroll
            for (int mt = 0; mt < 2; mt++) {
                const uint32_t* p = Pp + (mt * 16 + g) * 228 + k28 * 8;
                af[mt][0] = p[tig];
                af[mt][1] = p[8 * 228 + tig];
                af[mt][2] = p[tig + 4];
                af[mt][3] = p[8 * 228 + tig + 4];
            }
            bf[0] = vp[(k28 * 8 + tig) * 72 + warp * 8 + g];
            bf[1] = vp[(k28 * 8 + tig + 4) * 72 + warp * 8 + g];
            mma16(bacc[0], af[0], bf);
            mma16(bacc[1], af[1], bf);
        }

        #pragma unroll
        for (int mt = 0; mt < 2; mt++) {
            int r0 = mt * 16 + g, r1 = r0 + 8;
            int c = dn * 64 + warp * 8 + 2 * tig;
            if (r0 < JR) {
                const float2 sp2 = *(const float2*)(span + (long long)(s * JR + r0) * DD + c);
                *(float2*)(ctx + (long long)(s * JR + r0) * DD + c) =
                    make_float2(bacc[mt][0] + sp2.x, bacc[mt][1] + sp2.y);
            }
            if (r1 < JR) {
                const float2 sp2 = *(const float2*)(span + (long long)(s * JR + r1) * DD + c);
                *(float2*)(ctx + (long long)(s * JR + r1) * DD + c) =
                    make_float2(bacc[mt][2] + sp2.x, bacc[mt][3] + sp2.y);
            }
        }
        __syncthreads();
    }
}

// ---------------- span gather (fp32 -> span, fp16 -> cat left) -------------
__global__ void gather_kernel(const float* __restrict__ seq,
                              const int* __restrict__ starts,
                              float* __restrict__ out, half* __restrict__ cat)
{
    int sq = blockIdx.x;
    int s = sq / JR, q = sq - s * JR;
    int gstart = starts[s] + (s >> 3) * LSEQ;
    int idx = min(gstart + q, NB * LSEQ - 1);
    const float4* src = (const float4*)(seq + (long long)idx * DD);
    float4* dst = (float4*)(out + (long long)sq * DD);
    uint2* dst2 = (uint2*)(cat + (long long)sq * 2 * DD);
    for (int i = threadIdx.x; i < DD / 4; i += blockDim.x) {
        float4 v = src[i];
        dst[i] = v;
        uint2 u;
        u.x = pack2(v.x, v.y);
        u.y = pack2(v.z, v.w);
        dst2[i] = u;
    }
}

// ---------------- layernorm (fp16 strided output into cat right) -----------
__global__ __launch_bounds__(256)
void ln_kernel(const float* __restrict__ X, const float* __restrict__ g,
               const float* __restrict__ b, half* __restrict__ Y, int ostride)
{
    int r = blockIdx.x;
    int t = threadIdx.x;
    const float* x = X + (long long)r * DD;
    float v0 = x[t], v1 = x[t + 256], v2 = x[t + 512];
    __shared__ float red[8];

    float s = v0 + v1 + v2;
    #pragma unroll
    for (int o = 16; o; o >>= 1) s += __shfl_xor_sync(0xffffffffu, s, o);
    if ((t & 31) == 0) red[t >> 5] = s;
    __syncthreads();
    if (t == 0) { float z = 0.f; for (int i = 0; i < 8; i++) z += red[i]; red[0] = z; }
    __syncthreads();
    float mu = red[0] * (1.0f / DD);
    __syncthreads();

    float d0 = v0 - mu, d1 = v1 - mu, d2 = v2 - mu;
    float ss = d0 * d0 + d1 * d1 + d2 * d2;
    #pragma unroll
    for (int o = 16; o; o >>= 1) ss += __shfl_xor_sync(0xffffffffu, ss, o);
    if ((t & 31) == 0) red[t >> 5] = ss;
    __syncthreads();
    if (t == 0) { float z = 0.f; for (int i = 0; i < 8; i++) z += red[i]; red[0] = z; }
    __syncthreads();
    float inv = rsqrtf(red[0] * (1.0f / DD) + 1e-5f);

    half* y = Y + (long long)r * ostride;
    y[t]       = __float2half_rn(d0 * inv * g[t]       + b[t]);
    y[t + 256] = __float2half_rn(d1 * inv * g[t + 256] + b[t + 256]);
    y[t + 512] = __float2half_rn(d2 * inv * g[t + 512] + b[t + 512]);
}

// ---------------- unary score + masked softmax + pooling --------------------
__global__ __launch_bounds__(256)
void pool_kernel(const float* __restrict__ F2, const float* __restrict__ W_un,
                 const float* __restrict__ b_un, const int* __restrict__ starts,
                 const int* __restrict__ ends, half* __restrict__ pooled)
{
    int s = blockIdx.x;
    __shared__ float sc[JR];
    __shared__ float pr[32];
    int tid = threadIdx.x, warp = tid >> 5, lane = tid & 31;

    for (int q = warp; q < JR; q += 8) {
        const float* row = F2 + (long long)(s * JR + q) * DD;
        float acc = 0.f;
        for (int k = lane; k < DD; k += 32) acc += row[k] * W_un[k];
        #pragma unroll
        for (int o = 16; o; o >>= 1) acc += __shfl_xor_sync(0xffffffffu, acc, o);
        if (lane == 0) sc[q] = acc + b_un[0];
    }
    __syncthreads();

    if (tid < 32) {
        int width = ends[s] - starts[s] + 1;
        float v = -3.0e38f;
        if (tid < JR) {
            v = sc[tid];
            if (tid >= width) v += -10000.0f;
        }
        float m = v;
        #pragma unroll
        for (int o = 16; o; o >>= 1) m = fmaxf(m, __shfl_xor_sync(0xffffffffu, m, o));
        float e = (tid < JR) ? expf(v - m) : 0.f;
        float sum = e;
        #pragma unroll
        for (int o = 16; o; o >>= 1) sum += __shfl_xor_sync(0xffffffffu, sum, o);
        pr[tid] = (tid < JR) ? e / sum : 0.f;
    }
    __syncthreads();

    for (int o = tid; o < DD; o += 256) {
        float acc = 0.f;
        #pragma unroll
        for (int q = 0; q < JR; q++)
            acc += pr[q] * F2[(long long)(s * JR + q) * DD + o];
        pooled[(long long)s * DD + o] = __float2half_rn(acc);
    }
}

// ---------------- classifier ------------------------------------------------
__global__ void cls_kernel(const float* __restrict__ T, const float* __restrict__ Wc,
                           const float* __restrict__ bc, float* __restrict__ out)
{
    int s = blockIdx.x;
    int c = threadIdx.x >> 5, lane = threadIdx.x & 31;
    const float* t = T + (long long)s * DD;
    float acc = 0.f;
    for (int k = lane; k < DD; k += 32) acc += t[k] * Wc[k * 4 + c];
    #pragma unroll
    for (int o = 16; o; o >>= 1) acc += __shfl_xor_sync(0xffffffffu, acc, o);
    if (lane == 0) out[s * 4 + c] = acc + bc[c];
}

// ---------------- launcher --------------------------------------------------
extern "C" void kernel_launch(void* const* d_in, const int* in_sizes, int n_in,
                              void* d_out, int out_size)
{
    const float* enc_img  = (const float*)d_in[0];
    const float* seq      = (const float*)d_in[1];
    const int*   starts   = (const int*)d_in[3];
    const int*   ends     = (const int*)d_in[4];
    const float* W_align  = (const float*)d_in[5];
    const float* b_align  = (const float*)d_in[6];
    const float* Wq       = (const float*)d_in[7];
    const float* Wk       = (const float*)d_in[8];
    const float* Wv       = (const float*)d_in[9];
    const float* Wfc      = (const float*)d_in[10];
    const float* ln_g     = (const float*)d_in[11];
    const float* ln_b     = (const float*)d_in[12];
    const float* W_a1     = (const float*)d_in[13];
    const float* b_a1     = (const float*)d_in[14];
    const float* W_a2     = (const float*)d_in[15];
    const float* b_a2     = (const float*)d_in[16];
    const float* W_un     = (const float*)d_in[17];
    const float* b_un     = (const float*)d_in[18];
    const float* W_dense  = (const float*)d_in[19];
    const float* b_dense  = (const float*)d_in[20];
    const float* W_cls    = (const float*)d_in[21];
    const float* b_cls    = (const float*)d_in[22];
    float* out = (float*)d_out;

    half *ench, *resh, *kvh, *tilh, *cath, *h1h, *poolh;
    half *walh, *wkvh, *wth, *wa1h, *wa2h, *wdh;
    float *span, *ctx, *f2, *tb;
    uint32_t *vtp;
    cudaGetSymbolAddress((void**)&ench,  g_enc_h);
    cudaGetSymbolAddress((void**)&resh,  g_res_h);
    cudaGetSymbolAddress((void**)&kvh,   g_kv_h);
    cudaGetSymbolAddress((void**)&tilh,  g_til_h);
    cudaGetSymbolAddress((void**)&cath,  g_cat_h);
    cudaGetSymbolAddress((void**)&h1h,   g_h1_h);
    cudaGetSymbolAddress((void**)&poolh, g_pool_h);
    cudaGetSymbolAddress((void**)&span,  g_span);
    cudaGetSymbolAddress((void**)&ctx,   g_ctx);
    cudaGetSymbolAddress((void**)&f2,    g_f2);
    cudaGetSymbolAddress((void**)&tb,    g_t);
    cudaGetSymbolAddress((void**)&walh,  g_Walh);
    cudaGetSymbolAddress((void**)&wkvh,  g_Wkvh);
    cudaGetSymbolAddress((void**)&wth,   g_WTh);
    cudaGetSymbolAddress((void**)&wa1h,  g_Wa1h);
    cudaGetSymbolAddress((void**)&wa2h,  g_Wa2h);
    cudaGetSymbolAddress((void**)&wdh,   g_Wdh);
    cudaGetSymbolAddress((void**)&vtp,   g_vtilP);

    cudaFuncSetAttribute(gemmfp16<0, 0>, cudaFuncAttributeMaxDynamicSharedMemorySize, GEMM_SMEM);
    cudaFuncSetAttribute(gemmfp16<0, 1>, cudaFuncAttributeMaxDynamicSharedMemorySize, GEMM_SMEM);
    cudaFuncSetAttribute(gemmfp16<1, 0>, cudaFuncAttributeMaxDynamicSharedMemorySize, GEMM_SMEM);
    cudaFuncSetAttribute(gemmfp16<1, 1>, cudaFuncAttributeMaxDynamicSharedMemorySize, GEMM_SMEM);
    cudaFuncSetAttribute(fused_attn, cudaFuncAttributeMaxDynamicSharedMemorySize, ATTN_SMEM);

    // prep: fp32 -> fp16 conversions (8 plain jobs) + Wq head transpose
    CJobs cj;
    cj.j[0] = { enc_img, ench, 16 * 49, 2048, 2048, 2048 };
    cj.j[1] = { W_align, walh, 2048, 768, 768, 768 };
    cj.j[2] = { Wk, wkvh, 768, 6144, 6144, 12288 };
    cj.j[3] = { Wv, wkvh + 6144, 768, 6144, 6144, 12288 };
    cj.j[4] = { Wfc, wth + 8LL * 768 * 768, 6144, 768, 768, 768 };
    cj.j[5] = { W_a1, wa1h, 1536, 1536, 1536, 1536 };
    cj.j[6] = { W_a2, wa2h, 1536, 768, 768, 768 };
    cj.j[7] = { W_dense, wdh, 768, 768, 768, 768 };
    convJobs<<<dim3(256, 8), 256>>>(cj);
    transposeWqH<<<dim3(24, 24, 8), dim3(32, 8)>>>(Wq, wth);

    // 0) res split-K=2: partials into ctx scratch, then combine
    gemmfp16<0, 0><<<dim3(6, 7, 2), 256, GEMM_SMEM>>>(
        ench, walh, nullptr, ctx, SR, 768, 1024, 2048, 768, 768,
        1024LL, 1024LL * 768LL, (long long)SR * 768);
    resc_kernel<<<(SR * DD + 255) / 256, 256>>>(ctx, ctx + (long long)SR * DD, b_align, resh);

    // 1) kvproj = res @ [Wk|Wv]     [784,12288] half out
    gemmfp16<0, 1><<<dim3(96, 7, 1), 256, GEMM_SMEM>>>(
        resh, wkvh, nullptr, kvh, SR, 12288, 768, 768, 12288, 12288, 0, 0, 0);
    // 2) til (fp16): z<8 ktil_h = kproj_h @ WqT_h; z>=8 vtil_h = vproj_h @ Wfc_h
    gemmfp16<0, 1><<<dim3(6, 7, 16), 256, GEMM_SMEM>>>(
        kvh, wth, nullptr, tilh, SR, 768, 768, 12288, 768, 768,
        768LL, 768LL * 768LL, (long long)SR * 768);
    // 3) span gather
    gather_kernel<<<NQ, 192>>>(seq, starts, span, cath);
    // 4) vtil pack for AV
    vtilP_prep<<<2048, 256>>>(tilh, vtp);
    // 5) fused attention -> ctx
    fused_attn<<<NM, 256, ATTN_SMEM>>>(cath, tilh, vtp, span, ctx);
    // 6) layernorm -> cat right half
    ln_kernel<<<NQ, 256>>>(ctx, ln_g, ln_b, cath + DD, 2 * DD);
    // 7) h1 = tanh(cat @ W_a1 + b_a1)
    gemmfp16<1, 1><<<dim3(12, 30, 1), 256, GEMM_SMEM>>>(
        cath, wa1h, b_a1, h1h, NQ, 1536, 1536, 1536, 1536, 1536, 0, 0, 0);
    // 8) f2 = h1 @ W_a2 + b_a2
    gemmfp16<0, 0><<<dim3(6, 30, 1), 256, GEMM_SMEM>>>(
        h1h, wa2h, b_a2, f2, NQ, 768, 1536, 1536, 768, 768, 0, 0, 0);
    // 9) pool
    pool_kernel<<<NM, 256>>>(f2, W_un, b_un, starts, ends, poolh);
    // 10) dense
    gemmfp16<1, 0><<<dim3(6, 1, 1), 256, GEMM_SMEM>>>(
        poolh, wdh, b_dense, tb, NM, 768, 768, 768, 768, 768, 0, 0, 0);
    // 11) classifier
    cls_kernel<<<NM, 128>>>(tb, W_cls, b_cls, out);
}